// round 9
// baseline (speedup 1.0000x reference)
#include <cuda_runtime.h>
#include <math.h>
#include <stdint.h>

#define Bb 8
#define Nn 4096
#define DIM 768
#define HEADS 6
#define HD 128
#define QKVC 1536
#define NCHUNK 8
#define CHUNK (Nn/NCHUNK)   // 512
#define EPS 1e-12f

// ------------------ scratch (device globals: no allocs allowed) ------------------
__device__ float g_qkv[(size_t)Bb*Nn*QKVC];          // 201 MB
__device__ float g_nsum[Bb*QKVC];                    // column sum-of-squares
__device__ float g_inv[Bb*QKVC];                     // 1/max(norm,eps)
__device__ float g_P[NCHUNK][Bb*HEADS*HD*HD];        // attn partials, 25 MB
__device__ float g_attn[(size_t)Bb*HEADS*HD*HD];     // softmaxed attn, 3 MB
__device__ float g_tmp[(size_t)Bb*Nn*DIM];           // pre-projection output, 100 MB

// ------------------ tf32 helpers ------------------
__device__ __forceinline__ uint32_t f2tf32(float x) {
    uint32_t r;
    asm("cvt.rna.tf32.f32 %0, %1;" : "=r"(r) : "f"(x));
    return r;
}

// ------------------ tf32 tensor-core GEMM: 128x128x32 tile, 256 thr ------------------
// C[M,N] = A[M,K] @ B[K,N] (+bias), all row-major fp32, compute tf32.
template<int BIAS>
__global__ __launch_bounds__(256)
void tf32gemm(const float* __restrict__ A, const float* __restrict__ Bm,
              const float* __restrict__ bias, float* __restrict__ C,
              int M, int N, int K)
{
    // A stride 44: bank = (12*m + k) mod 32 -> conflict-free frags, float4-aligned.
    // B stride 168: bank = (8*k + n) mod 32 -> conflict-free frags, float4-aligned.
    __shared__ uint32_t As[128][44];
    __shared__ uint32_t Bs[32][168];

    const int tid  = threadIdx.x;
    const int m0   = blockIdx.y * 128, n0 = blockIdx.x * 128;
    const int warp = tid >> 5, lane = tid & 31;
    const int wm   = warp >> 1, wn = warp & 1;     // warp grid 4(m) x 2(n)
    const int g    = lane >> 2, tg = lane & 3;

    float acc[2][8][4];
#pragma unroll
    for (int mt = 0; mt < 2; mt++)
#pragma unroll
        for (int nt = 0; nt < 8; nt++)
#pragma unroll
            for (int i = 0; i < 4; i++) acc[mt][nt][i] = 0.f;

    const int arow = tid >> 3, acol = (tid & 7) * 4;   // A tile 128x32: 4 rows/thread stride 32
    const int brow = tid >> 5, bcol = (tid & 31) * 4;  // B tile 32x128: 4 rows/thread stride 8
    const float* Ap = A + (size_t)(m0 + arow) * K + acol;
    const float* Bp = Bm + (size_t)brow * N + n0 + bcol;

    float4 ar[4], br[4];
#pragma unroll
    for (int i = 0; i < 4; i++) ar[i] = *(const float4*)(Ap + (size_t)(i * 32) * K);
#pragma unroll
    for (int i = 0; i < 4; i++) br[i] = *(const float4*)(Bp + (size_t)(i * 8) * N);

    const int KT = K / 32;
    for (int kt = 0; kt < KT; kt++) {
        // convert + store current tile to smem
#pragma unroll
        for (int i = 0; i < 4; i++) {
            uint4 w;
            w.x = f2tf32(ar[i].x); w.y = f2tf32(ar[i].y);
            w.z = f2tf32(ar[i].z); w.w = f2tf32(ar[i].w);
            *(uint4*)&As[arow + i * 32][acol] = w;
        }
#pragma unroll
        for (int i = 0; i < 4; i++) {
            uint4 w;
            w.x = f2tf32(br[i].x); w.y = f2tf32(br[i].y);
            w.z = f2tf32(br[i].z); w.w = f2tf32(br[i].w);
            *(uint4*)&Bs[brow + i * 8][bcol] = w;
        }
        __syncthreads();

        // prefetch next tile into registers
        if (kt + 1 < KT) {
            const float* Ap2 = Ap + (kt + 1) * 32;
            const float* Bp2 = Bp + (size_t)(kt + 1) * 32 * N;
#pragma unroll
            for (int i = 0; i < 4; i++) ar[i] = *(const float4*)(Ap2 + (size_t)(i * 32) * K);
#pragma unroll
            for (int i = 0; i < 4; i++) br[i] = *(const float4*)(Bp2 + (size_t)(i * 8) * N);
        }

        // compute 32 k-steps (4 x k8)
#pragma unroll
        for (int ks = 0; ks < 4; ks++) {
            const int kb = ks * 8;
            uint32_t af[2][4];
#pragma unroll
            for (int mt = 0; mt < 2; mt++) {
                int mr = wm * 32 + mt * 16 + g;
                af[mt][0] = As[mr][kb + tg];
                af[mt][1] = As[mr + 8][kb + tg];
                af[mt][2] = As[mr][kb + tg + 4];
                af[mt][3] = As[mr + 8][kb + tg + 4];
            }
            uint32_t bf[8][2];
#pragma unroll
            for (int nt = 0; nt < 8; nt++) {
                int nc = wn * 64 + nt * 8 + g;
                bf[nt][0] = Bs[kb + tg][nc];
                bf[nt][1] = Bs[kb + tg + 4][nc];
            }
#pragma unroll
            for (int mt = 0; mt < 2; mt++)
#pragma unroll
                for (int nt = 0; nt < 8; nt++) {
                    float* c = acc[mt][nt];
                    asm volatile(
                        "mma.sync.aligned.m16n8k8.row.col.f32.tf32.tf32.f32 "
                        "{%0,%1,%2,%3},{%4,%5,%6,%7},{%8,%9},{%0,%1,%2,%3};"
                        : "+f"(c[0]), "+f"(c[1]), "+f"(c[2]), "+f"(c[3])
                        : "r"(af[mt][0]), "r"(af[mt][1]), "r"(af[mt][2]), "r"(af[mt][3]),
                          "r"(bf[nt][0]), "r"(bf[nt][1]));
                }
        }
        __syncthreads();
    }

    // epilogue
#pragma unroll
    for (int mt = 0; mt < 2; mt++) {
#pragma unroll
        for (int half = 0; half < 2; half++) {
            int row = m0 + wm * 32 + mt * 16 + g + half * 8;
#pragma unroll
            for (int nt = 0; nt < 8; nt++) {
                int col = n0 + wn * 64 + nt * 8 + tg * 2;
                float2 o;
                o.x = acc[mt][nt][half * 2 + 0];
                o.y = acc[mt][nt][half * 2 + 1];
                if (BIAS) { o.x += bias[col]; o.y += bias[col + 1]; }
                *(float2*)&C[(size_t)row * N + col] = o;
            }
        }
    }
}

// ------------------ zero helper ------------------
__global__ void zero_nsum() {
    int i = blockIdx.x * 256 + threadIdx.x;
    if (i < Bb * QKVC) g_nsum[i] = 0.f;
}

// ------------------ column sum-of-squares partials ------------------
__global__ __launch_bounds__(256)
void partial_norm()
{
    int col = blockIdx.x * 256 + threadIdx.x;
    int ch = blockIdx.y, b = blockIdx.z;
    const float* p = g_qkv + ((size_t)b * Nn + (size_t)ch * CHUNK) * QKVC + col;
    float s = 0.f;
    for (int n = 0; n < CHUNK; n++) {
        float v = p[(size_t)n * QKVC];
        s += v * v;
    }
    atomicAdd(&g_nsum[b * QKVC + col], s);
}

__global__ void inv_norm() {
    int i = blockIdx.x * 256 + threadIdx.x;
    if (i < Bb * QKVC) {
        float nr = sqrtf(g_nsum[i]);
        g_inv[i] = 1.f / fmaxf(nr, EPS);
    }
}

// ------------------ attn partials: per (h,b,chunk), 128x128 over 512 tokens ------------------
__global__ __launch_bounds__(256)
void attn_partial()
{
    int h = blockIdx.x, b = blockIdx.y, ch = blockIdx.z;
    __shared__ float Qs[16][128];
    __shared__ float Ks[16][128];
    int tid = threadIdx.x;
    int tx = tid & 15, ty = tid >> 4;
    float acc[8][8];
#pragma unroll
    for (int i = 0; i < 8; i++)
#pragma unroll
        for (int j = 0; j < 8; j++) acc[i][j] = 0.f;

    const float* qbase = g_qkv + ((size_t)b * Nn + (size_t)ch * CHUNK) * QKVC + h * HD;
    const float* kbase = qbase + DIM;
    int lrow = tid >> 5;
    int lcol = (tid & 31) * 4;

    for (int n0 = 0; n0 < CHUNK; n0 += 16) {
#pragma unroll
        for (int p = 0; p < 2; p++) {
            int n = n0 + lrow + p * 8;
            float4 qv = *(const float4*)(qbase + (size_t)n * QKVC + lcol);
            *(float4*)&Qs[lrow + p * 8][lcol] = qv;
            float4 kv = *(const float4*)(kbase + (size_t)n * QKVC + lcol);
            *(float4*)&Ks[lrow + p * 8][lcol] = kv;
        }
        __syncthreads();
#pragma unroll
        for (int n = 0; n < 16; n++) {
            float a[8], bv[8];
#pragma unroll
            for (int i = 0; i < 8; i++) a[i] = Qs[n][ty * 8 + i];
#pragma unroll
            for (int j = 0; j < 8; j++) bv[j] = Ks[n][tx * 8 + j];
#pragma unroll
            for (int i = 0; i < 8; i++)
#pragma unroll
                for (int j = 0; j < 8; j++) acc[i][j] += a[i] * bv[j];
        }
        __syncthreads();
    }

    float* Pp = &g_P[ch][(size_t)(b * HEADS + h) * HD * HD];
#pragma unroll
    for (int i = 0; i < 8; i++) {
        size_t row = (size_t)(ty * 8 + i) * HD + tx * 8;
#pragma unroll
        for (int j = 0; j < 8; j += 4) {
            float4 o;
            o.x = acc[i][j + 0]; o.y = acc[i][j + 1];
            o.z = acc[i][j + 2]; o.w = acc[i][j + 3];
            *(float4*)&Pp[row + j] = o;
        }
    }
}

// ------------------ sum partials + scale + softmax ------------------
__global__ __launch_bounds__(128)
void softmax_rows(const float* __restrict__ temperature)
{
    int c = blockIdx.x, h = blockIdx.y, b = blockIdx.z;
    int d = threadIdx.x;
    size_t off = ((size_t)(b * HEADS + h) * HD + c) * HD + d;

    float s = 0.f;
#pragma unroll
    for (int ch = 0; ch < NCHUNK; ch++) s += g_P[ch][off];

    float scale = g_inv[b * QKVC + h * HD + c] *
                  g_inv[b * QKVC + DIM + h * HD + d] *
                  temperature[h];
    float val = s * scale;

    __shared__ float red[128];
    red[d] = val;
    __syncthreads();
    for (int o = 64; o >= 1; o >>= 1) {
        if (d < o) red[d] = fmaxf(red[d], red[d + o]);
        __syncthreads();
    }
    float mx = red[0];
    __syncthreads();
    float e = expf(val - mx);
    red[d] = e;
    __syncthreads();
    for (int o = 64; o >= 1; o >>= 1) {
        if (d < o) red[d] += red[d + o];
        __syncthreads();
    }
    float inv = 1.f / red[0];
    g_attn[off] = e * inv;
}

// ------------------ out_tmp = attn @ v ------------------
__global__ __launch_bounds__(256)
void av_kernel(const float* __restrict__ y)
{
    int nblk = blockIdx.x, h = blockIdx.y, b = blockIdx.z;
    int tid = threadIdx.x;
    int nl = tid >> 3;
    int cb = (tid & 7) * 16;

    __shared__ float Ys[32][36];
    __shared__ float At[32][128];

    float acc[16];
#pragma unroll
    for (int j = 0; j < 16; j++) acc[j] = 0.f;

    const float* attnp = g_attn + (size_t)(b * HEADS + h) * HD * HD;
    const float* ybase = y + ((size_t)b * Nn + (size_t)nblk * 32) * DIM + h * HD;

    for (int d0 = 0; d0 < HD; d0 += 32) {
        {
            int r = tid >> 3, c4 = (tid & 7) * 4;
            float4 yv = *(const float4*)(ybase + (size_t)r * DIM + d0 + c4);
            *(float4*)&Ys[r][c4] = yv;
        }
#pragma unroll
        for (int pass = 0; pass < 4; pass++) {
            int c = pass * 32 + (tid >> 3);
            int dl = (tid & 7) * 4;
            float4 a = *(const float4*)(attnp + (size_t)c * HD + d0 + dl);
            At[dl + 0][c] = a.x;
            At[dl + 1][c] = a.y;
            At[dl + 2][c] = a.z;
            At[dl + 3][c] = a.w;
        }
        __syncthreads();
#pragma unroll
        for (int dd = 0; dd < 32; dd++) {
            float yv = Ys[nl][dd];
#pragma unroll
            for (int j = 0; j < 16; j++) acc[j] += yv * At[dd][cb + j];
        }
        __syncthreads();
    }

    float* op = g_tmp + ((size_t)b * Nn + (size_t)nblk * 32 + nl) * DIM + h * HD + cb;
#pragma unroll
    for (int j = 0; j < 16; j += 4) {
        float4 o;
        o.x = acc[j + 0]; o.y = acc[j + 1]; o.z = acc[j + 2]; o.w = acc[j + 3];
        *(float4*)(op + j) = o;
    }
}

// ------------------ launch ------------------
extern "C" void kernel_launch(void* const* d_in, const int* in_sizes, int n_in,
                              void* d_out, int out_size)
{
    const float* x     = (const float*)d_in[0];
    const float* y     = (const float*)d_in[1];
    const float* W_qkv = (const float*)d_in[2];
    const float* temp  = (const float*)d_in[3];
    const float* W_prj = (const float*)d_in[4];
    const float* b_prj = (const float*)d_in[5];
    float* out = (float*)d_out;

    float *qkv_p, *tmp_p;
    cudaGetSymbolAddress((void**)&qkv_p, g_qkv);
    cudaGetSymbolAddress((void**)&tmp_p, g_tmp);

    // 1. qkv = x @ W_qkv   [32768 x 768] @ [768 x 1536] (tf32 tensor cores)
    tf32gemm<0><<<dim3(QKVC / 128, (Bb * Nn) / 128), 256>>>(
        x, W_qkv, nullptr, qkv_p, Bb * Nn, QKVC, DIM);

    // 2. column norms of q,k over token dim
    zero_nsum<<<(Bb * QKVC + 255) / 256, 256>>>();
    partial_norm<<<dim3(QKVC / 256, NCHUNK, Bb), 256>>>();
    inv_norm<<<(Bb * QKVC + 255) / 256, 256>>>();

    // 3. attn partials per (h, b, chunk)
    attn_partial<<<dim3(HEADS, Bb, NCHUNK), 256>>>();

    // 4. sum + scale + softmax
    softmax_rows<<<dim3(HD, HEADS, Bb), 128>>>(temp);

    // 5. out_tmp = attn @ v
    av_kernel<<<dim3(Nn / 32, HEADS, Bb), 256>>>(y);

    // 6. out = out_tmp @ W_proj + b (tf32 tensor cores)
    tf32gemm<1><<<dim3(DIM / 128, (Bb * Nn) / 128), 256>>>(
        tmp_p, W_prj, b_prj, out, Bb * Nn, DIM, DIM);
}

// round 10
// speedup vs baseline: 1.8936x; 1.8936x over previous
#include <cuda_runtime.h>
#include <math.h>
#include <stdint.h>

#define Bb 8
#define Nn 4096
#define DIM 768
#define HEADS 6
#define HD 128
#define QKVC 1536
#define NCHUNK 8
#define CHUNK (Nn/NCHUNK)   // 512
#define EPS 1e-12f

// ------------------ scratch (device globals: no allocs allowed) ------------------
__device__ float g_qkv[(size_t)Bb*Nn*QKVC];          // 201 MB
__device__ float g_xr[(size_t)Bb*Nn*DIM];            // tf32-rounded x, 100 MB
__device__ float g_wqkv[DIM*QKVC];                   // tf32-rounded W_qkv
__device__ float g_wproj[DIM*DIM];                   // tf32-rounded W_proj
__device__ float g_nsum[Bb*QKVC];
__device__ float g_inv[Bb*QKVC];
__device__ float g_P[NCHUNK][Bb*HEADS*HD*HD];        // attn partials, 25 MB
__device__ float g_attn[(size_t)Bb*HEADS*HD*HD];     // softmaxed attn (tf32-rounded)
__device__ float g_tmp[(size_t)Bb*Nn*DIM];           // pre-projection output (tf32-rounded)

// ------------------ helpers ------------------
__device__ __forceinline__ uint32_t f2tf32(float x) {
    uint32_t r;
    asm("cvt.rna.tf32.f32 %0, %1;" : "=r"(r) : "f"(x));
    return r;
}
__device__ __forceinline__ float roundtf(float x) {
    return __uint_as_float(f2tf32(x));
}
__device__ __forceinline__ void cp16(void* dst, const void* src) {
    uint32_t d = (uint32_t)__cvta_generic_to_shared(dst);
    asm volatile("cp.async.cg.shared.global [%0], [%1], 16;" :: "r"(d), "l"(src));
}
__device__ __forceinline__ void mma_tf32(float* c, const uint32_t* a, const uint32_t* b) {
    asm volatile(
        "mma.sync.aligned.m16n8k8.row.col.f32.tf32.tf32.f32 "
        "{%0,%1,%2,%3},{%4,%5,%6,%7},{%8,%9},{%0,%1,%2,%3};"
        : "+f"(c[0]), "+f"(c[1]), "+f"(c[2]), "+f"(c[3])
        : "r"(a[0]), "r"(a[1]), "r"(a[2]), "r"(a[3]), "r"(b[0]), "r"(b[1]));
}

// ------------------ elementwise tf32 rounding ------------------
__global__ void round_tf32(const float* __restrict__ in, float* __restrict__ out, int n4) {
    int i = blockIdx.x * 256 + threadIdx.x;
    if (i < n4) {
        float4 v = ((const float4*)in)[i];
        v.x = roundtf(v.x); v.y = roundtf(v.y);
        v.z = roundtf(v.z); v.w = roundtf(v.w);
        ((float4*)out)[i] = v;
    }
}

// ------------------ tf32 GEMM, cp.async double-buffered, 128x128x32 ------------------
// Inputs must be pre-rounded to tf32 values. Dynamic smem: 2*(128*36 + 32*136)*4 B.
#define AST 36
#define BST 136
#define GEMM_SMEM (2*(128*AST + 32*BST)*4)

template<int BIAS>
__global__ __launch_bounds__(256)
void tf32gemm_db(const float* __restrict__ A, const float* __restrict__ Bm,
                 const float* __restrict__ bias, float* __restrict__ C,
                 int M, int N, int K)
{
    extern __shared__ float sm[];
    float* AsBase = sm;                 // [2][128*AST]
    float* BsBase = sm + 2 * 128 * AST; // [2][32*BST]

    const int tid  = threadIdx.x;
    const int m0   = blockIdx.y * 128, n0 = blockIdx.x * 128;
    const int warp = tid >> 5, lane = tid & 31;
    const int wm   = warp >> 1, wn = warp & 1;
    const int g    = lane >> 2, tg = lane & 3;

    float acc[2][8][4];
#pragma unroll
    for (int mt = 0; mt < 2; mt++)
#pragma unroll
        for (int nt = 0; nt < 8; nt++)
#pragma unroll
            for (int i = 0; i < 4; i++) acc[mt][nt][i] = 0.f;

    // cp.async mapping: A tile 128x32 (8 chunks/row), B tile 32x128 (32 chunks/row)
    const int arow = tid >> 1, acol = (tid & 1) * 16;
    const int brow = tid >> 3, bcol = (tid & 7) * 16;
    const float* Ag = A + (size_t)(m0 + arow) * K + acol;
    const float* Bg = Bm + (size_t)brow * N + n0 + bcol;
    float* Asd = AsBase + arow * AST + acol;
    float* Bsd = BsBase + brow * BST + bcol;

    const int KT = K / 32;

    // prologue: stage 0
    {
#pragma unroll
        for (int i = 0; i < 4; i++) cp16(Asd + i * 4, Ag + i * 4);
#pragma unroll
        for (int i = 0; i < 4; i++) cp16(Bsd + i * 4, Bg + i * 4);
        asm volatile("cp.async.commit_group;");
    }

    for (int kt = 0; kt < KT; kt++) {
        const int st = kt & 1;
        if (kt + 1 < KT) {
            const int st2 = st ^ 1;
            const float* Ap = Ag + (kt + 1) * 32;
            const float* Bp = Bg + (size_t)(kt + 1) * 32 * N;
            float* Ad = Asd + st2 * 128 * AST;
            float* Bd = Bsd + st2 * 32 * BST;
#pragma unroll
            for (int i = 0; i < 4; i++) cp16(Ad + i * 4, Ap + i * 4);
#pragma unroll
            for (int i = 0; i < 4; i++) cp16(Bd + i * 4, Bp + i * 4);
            asm volatile("cp.async.commit_group;");
            asm volatile("cp.async.wait_group 1;");
        } else {
            asm volatile("cp.async.wait_group 0;");
        }
        __syncthreads();

        const uint32_t* As = (const uint32_t*)(AsBase + st * 128 * AST);
        const uint32_t* Bs = (const uint32_t*)(BsBase + st * 32 * BST);
#pragma unroll
        for (int ks = 0; ks < 4; ks++) {
            const int kb = ks * 8;
            uint32_t af[2][4];
#pragma unroll
            for (int mt = 0; mt < 2; mt++) {
                int mr = wm * 32 + mt * 16 + g;
                af[mt][0] = As[(size_t)mr * AST + kb + tg];
                af[mt][1] = As[(size_t)(mr + 8) * AST + kb + tg];
                af[mt][2] = As[(size_t)mr * AST + kb + tg + 4];
                af[mt][3] = As[(size_t)(mr + 8) * AST + kb + tg + 4];
            }
            uint32_t bf[8][2];
#pragma unroll
            for (int nt = 0; nt < 8; nt++) {
                int nc = wn * 64 + nt * 8 + g;
                bf[nt][0] = Bs[(size_t)(kb + tg) * BST + nc];
                bf[nt][1] = Bs[(size_t)(kb + tg + 4) * BST + nc];
            }
#pragma unroll
            for (int mt = 0; mt < 2; mt++)
#pragma unroll
                for (int nt = 0; nt < 8; nt++) mma_tf32(acc[mt][nt], af[mt], bf[nt]);
        }
        __syncthreads();
    }

#pragma unroll
    for (int mt = 0; mt < 2; mt++) {
#pragma unroll
        for (int half = 0; half < 2; half++) {
            int row = m0 + wm * 32 + mt * 16 + g + half * 8;
#pragma unroll
            for (int nt = 0; nt < 8; nt++) {
                int col = n0 + wn * 64 + nt * 8 + tg * 2;
                float2 o;
                o.x = acc[mt][nt][half * 2 + 0];
                o.y = acc[mt][nt][half * 2 + 1];
                if (BIAS) { o.x += bias[col]; o.y += bias[col + 1]; }
                *(float2*)&C[(size_t)row * N + col] = o;
            }
        }
    }
}

// ------------------ norms ------------------
__global__ void zero_nsum() {
    int i = blockIdx.x * 256 + threadIdx.x;
    if (i < Bb * QKVC) g_nsum[i] = 0.f;
}

__global__ __launch_bounds__(256)
void partial_norm()
{
    int col = blockIdx.x * 256 + threadIdx.x;
    int ch = blockIdx.y, b = blockIdx.z;
    const float* p = g_qkv + ((size_t)b * Nn + (size_t)ch * CHUNK) * QKVC + col;
    float s = 0.f;
    for (int n = 0; n < CHUNK; n++) {
        float v = p[(size_t)n * QKVC];
        s += v * v;
    }
    atomicAdd(&g_nsum[b * QKVC + col], s);
}

__global__ void inv_norm() {
    int i = blockIdx.x * 256 + threadIdx.x;
    if (i < Bb * QKVC) {
        float nr = sqrtf(g_nsum[i]);
        g_inv[i] = 1.f / fmaxf(nr, EPS);
    }
}

// ------------------ attn partials via tf32 mma: per (h,b,chunk) ------------------
// C[c,c'] = sum_n q[n,c] * k[n,c'], K = 512 tokens per chunk.
__global__ __launch_bounds__(256)
void attn_mma()
{
    int h = blockIdx.x, b = blockIdx.y, ch = blockIdx.z;
    __shared__ uint32_t Qs[32][136];
    __shared__ uint32_t Ks[32][136];

    const int tid  = threadIdx.x;
    const int warp = tid >> 5, lane = tid & 31;
    const int wm   = warp >> 1, wn = warp & 1;
    const int g    = lane >> 2, tg = lane & 3;

    float acc[2][8][4];
#pragma unroll
    for (int mt = 0; mt < 2; mt++)
#pragma unroll
        for (int nt = 0; nt < 8; nt++)
#pragma unroll
            for (int i = 0; i < 4; i++) acc[mt][nt][i] = 0.f;

    const float* qbase = g_qkv + ((size_t)b * Nn + (size_t)ch * CHUNK) * QKVC + h * HD;
    const float* kbase = qbase + DIM;

    const int lrow = tid >> 3;          // 0..31 token row
    const int lcb  = (tid & 7) * 16;    // 16 channels per thread

    for (int n0 = 0; n0 < CHUNK; n0 += 32) {
        const float* qp = qbase + (size_t)(n0 + lrow) * QKVC + lcb;
        const float* kp = kbase + (size_t)(n0 + lrow) * QKVC + lcb;
#pragma unroll
        for (int i = 0; i < 4; i++) {
            float4 qv = *(const float4*)(qp + i * 4);
            Qs[lrow][lcb + i * 4 + 0] = f2tf32(qv.x);
            Qs[lrow][lcb + i * 4 + 1] = f2tf32(qv.y);
            Qs[lrow][lcb + i * 4 + 2] = f2tf32(qv.z);
            Qs[lrow][lcb + i * 4 + 3] = f2tf32(qv.w);
            float4 kv = *(const float4*)(kp + i * 4);
            Ks[lrow][lcb + i * 4 + 0] = f2tf32(kv.x);
            Ks[lrow][lcb + i * 4 + 1] = f2tf32(kv.y);
            Ks[lrow][lcb + i * 4 + 2] = f2tf32(kv.z);
            Ks[lrow][lcb + i * 4 + 3] = f2tf32(kv.w);
        }
        __syncthreads();
#pragma unroll
        for (int ks = 0; ks < 4; ks++) {
            const int kb = ks * 8;
            uint32_t af[2][4];
#pragma unroll
            for (int mt = 0; mt < 2; mt++) {
                int cm = wm * 32 + mt * 16 + g;
                af[mt][0] = Qs[kb + tg][cm];
                af[mt][1] = Qs[kb + tg][cm + 8];
                af[mt][2] = Qs[kb + tg + 4][cm];
                af[mt][3] = Qs[kb + tg + 4][cm + 8];
            }
            uint32_t bf[8][2];
#pragma unroll
            for (int nt = 0; nt < 8; nt++) {
                int nc = wn * 64 + nt * 8 + g;
                bf[nt][0] = Ks[kb + tg][nc];
                bf[nt][1] = Ks[kb + tg + 4][nc];
            }
#pragma unroll
            for (int mt = 0; mt < 2; mt++)
#pragma unroll
                for (int nt = 0; nt < 8; nt++) mma_tf32(acc[mt][nt], af[mt], bf[nt]);
        }
        __syncthreads();
    }

    float* Pp = &g_P[ch][(size_t)(b * HEADS + h) * HD * HD];
#pragma unroll
    for (int mt = 0; mt < 2; mt++) {
#pragma unroll
        for (int half = 0; half < 2; half++) {
            int row = wm * 32 + mt * 16 + g + half * 8;
#pragma unroll
            for (int nt = 0; nt < 8; nt++) {
                int col = wn * 64 + nt * 8 + tg * 2;
                float2 o;
                o.x = acc[mt][nt][half * 2 + 0];
                o.y = acc[mt][nt][half * 2 + 1];
                *(float2*)&Pp[(size_t)row * HD + col] = o;
            }
        }
    }
}

// ------------------ sum partials + scale + softmax (rounds output to tf32) ------------------
__global__ __launch_bounds__(128)
void softmax_rows(const float* __restrict__ temperature)
{
    int c = blockIdx.x, h = blockIdx.y, b = blockIdx.z;
    int d = threadIdx.x;
    size_t off = ((size_t)(b * HEADS + h) * HD + c) * HD + d;

    float s = 0.f;
#pragma unroll
    for (int ch = 0; ch < NCHUNK; ch++) s += g_P[ch][off];

    float scale = g_inv[b * QKVC + h * HD + c] *
                  g_inv[b * QKVC + DIM + h * HD + d] *
                  temperature[h];
    float val = s * scale;

    __shared__ float red[128];
    red[d] = val;
    __syncthreads();
    for (int o = 64; o >= 1; o >>= 1) {
        if (d < o) red[d] = fmaxf(red[d], red[d + o]);
        __syncthreads();
    }
    float mx = red[0];
    __syncthreads();
    float e = expf(val - mx);
    red[d] = e;
    __syncthreads();
    for (int o = 64; o >= 1; o >>= 1) {
        if (d < o) red[d] += red[d + o];
        __syncthreads();
    }
    float inv = 1.f / red[0];
    g_attn[off] = roundtf(e * inv);
}

// ------------------ out_tmp = attn @ v via tf32 mma ------------------
// C[token, c] = sum_d y[token, d] * attn[c, d]; per (b,h), 128-token tiles.
__global__ __launch_bounds__(256)
void av_mma(const float* __restrict__ y)
{
    int mblk = blockIdx.x, h = blockIdx.y, b = blockIdx.z;
    __shared__ uint32_t Ys[128][36];
    __shared__ uint32_t At[128][36];   // attn [c][d-tile]

    const int tid  = threadIdx.x;
    const int warp = tid >> 5, lane = tid & 31;
    const int wm   = warp >> 1, wn = warp & 1;
    const int g    = lane >> 2, tg = lane & 3;

    float acc[2][8][4];
#pragma unroll
    for (int mt = 0; mt < 2; mt++)
#pragma unroll
        for (int nt = 0; nt < 8; nt++)
#pragma unroll
            for (int i = 0; i < 4; i++) acc[mt][nt][i] = 0.f;

    const int m0 = mblk * 128;
    const float* ybase = y + ((size_t)b * Nn + m0) * DIM + h * HD;
    const float* attnp = g_attn + (size_t)(b * HEADS + h) * HD * HD;

    const int lrow = tid >> 1;           // 0..127
    const int lcb  = (tid & 1) * 16;     // 16 d per thread

    for (int d0 = 0; d0 < HD; d0 += 32) {
        const float* yp = ybase + (size_t)lrow * DIM + d0 + lcb;
        const float* ap = attnp + (size_t)lrow * HD + d0 + lcb;
#pragma unroll
        for (int i = 0; i < 4; i++) {
            float4 yv = *(const float4*)(yp + i * 4);
            Ys[lrow][lcb + i * 4 + 0] = f2tf32(yv.x);
            Ys[lrow][lcb + i * 4 + 1] = f2tf32(yv.y);
            Ys[lrow][lcb + i * 4 + 2] = f2tf32(yv.z);
            Ys[lrow][lcb + i * 4 + 3] = f2tf32(yv.w);
            // attn already tf32-rounded by softmax
            *(uint4*)&At[lrow][lcb + i * 4] = *(const uint4*)(ap + i * 4);
        }
        __syncthreads();
#pragma unroll
        for (int ks = 0; ks < 4; ks++) {
            const int kb = ks * 8;
            uint32_t af[2][4];
#pragma unroll
            for (int mt = 0; mt < 2; mt++) {
                int mr = wm * 32 + mt * 16 + g;
                af[mt][0] = Ys[mr][kb + tg];
                af[mt][1] = Ys[mr + 8][kb + tg];
                af[mt][2] = Ys[mr][kb + tg + 4];
                af[mt][3] = Ys[mr + 8][kb + tg + 4];
            }
            uint32_t bf[8][2];
#pragma unroll
            for (int nt = 0; nt < 8; nt++) {
                int nc = wn * 64 + nt * 8 + g;
                bf[nt][0] = At[nc][kb + tg];
                bf[nt][1] = At[nc][kb + tg + 4];
            }
#pragma unroll
            for (int mt = 0; mt < 2; mt++)
#pragma unroll
                for (int nt = 0; nt < 8; nt++) mma_tf32(acc[mt][nt], af[mt], bf[nt]);
        }
        __syncthreads();
    }

    // epilogue: write tf32-rounded (feeds proj GEMM)
#pragma unroll
    for (int mt = 0; mt < 2; mt++) {
#pragma unroll
        for (int half = 0; half < 2; half++) {
            int row = m0 + wm * 32 + mt * 16 + g + half * 8;
#pragma unroll
            for (int nt = 0; nt < 8; nt++) {
                int col = wn * 64 + nt * 8 + tg * 2;
                float2 o;
                o.x = roundtf(acc[mt][nt][half * 2 + 0]);
                o.y = roundtf(acc[mt][nt][half * 2 + 1]);
                *(float2*)&g_tmp[((size_t)b * Nn + row) * DIM + h * HD + col] = o;
            }
        }
    }
}

// ------------------ launch ------------------
extern "C" void kernel_launch(void* const* d_in, const int* in_sizes, int n_in,
                              void* d_out, int out_size)
{
    const float* x     = (const float*)d_in[0];
    const float* y     = (const float*)d_in[1];
    const float* W_qkv = (const float*)d_in[2];
    const float* temp  = (const float*)d_in[3];
    const float* W_prj = (const float*)d_in[4];
    const float* b_prj = (const float*)d_in[5];
    float* out = (float*)d_out;

    float *qkv_p, *tmp_p, *xr_p, *wqkv_p, *wproj_p;
    cudaGetSymbolAddress((void**)&qkv_p, g_qkv);
    cudaGetSymbolAddress((void**)&tmp_p, g_tmp);
    cudaGetSymbolAddress((void**)&xr_p, g_xr);
    cudaGetSymbolAddress((void**)&wqkv_p, g_wqkv);
    cudaGetSymbolAddress((void**)&wproj_p, g_wproj);

    static bool attr_done = false;
    if (!attr_done) {
        cudaFuncSetAttribute(tf32gemm_db<0>, cudaFuncAttributeMaxDynamicSharedMemorySize, GEMM_SMEM);
        cudaFuncSetAttribute(tf32gemm_db<1>, cudaFuncAttributeMaxDynamicSharedMemorySize, GEMM_SMEM);
        attr_done = true;
    }

    // 0. pre-round operands to tf32 values
    {
        int n4x = Bb * Nn * DIM / 4;
        round_tf32<<<(n4x + 255) / 256, 256>>>(x, xr_p, n4x);
        int n4q = DIM * QKVC / 4;
        round_tf32<<<(n4q + 255) / 256, 256>>>(W_qkv, wqkv_p, n4q);
        int n4p = DIM * DIM / 4;
        round_tf32<<<(n4p + 255) / 256, 256>>>(W_prj, wproj_p, n4p);
    }

    // 1. qkv = x @ W_qkv  (tf32 tensor cores, cp.async double-buffered)
    tf32gemm_db<0><<<dim3(QKVC / 128, (Bb * Nn) / 128), 256, GEMM_SMEM>>>(
        xr_p, wqkv_p, nullptr, qkv_p, Bb * Nn, QKVC, DIM);

    // 2. column norms of q,k over token dim (fp32, from un-rounded qkv output)
    zero_nsum<<<(Bb * QKVC + 255) / 256, 256>>>();
    partial_norm<<<dim3(QKVC / 256, NCHUNK, Bb), 256>>>();
    inv_norm<<<(Bb * QKVC + 255) / 256, 256>>>();

    // 3. attn partials (tf32 mma)
    attn_mma<<<dim3(HEADS, Bb, NCHUNK), 256>>>();

    // 4. sum + scale + softmax (writes tf32-rounded attn)
    softmax_rows<<<dim3(HD, HEADS, Bb), 128>>>(temp);

    // 5. out_tmp = attn @ v (tf32 mma, writes tf32-rounded)
    av_mma<<<dim3(Nn / 128, HEADS, Bb), 256>>>(y);

    // 6. out = out_tmp @ W_proj + b (tf32 tensor cores)
    tf32gemm_db<1><<<dim3(DIM / 128, (Bb * Nn) / 128), 256, GEMM_SMEM>>>(
        tmp_p, wproj_p, b_prj, out, Bb * Nn, DIM, DIM);
}

// round 11
// speedup vs baseline: 1.8943x; 1.0004x over previous
#include <cuda_runtime.h>
#include <math.h>
#include <stdint.h>

#define Bb 8
#define Nn 4096
#define DIM 768
#define HEADS 6
#define HD 128
#define QKVC 1536
#define NCHUNK 8
#define CHUNK (Nn/NCHUNK)   // 512
#define EPS 1e-12f

// ------------------ scratch (device globals: no allocs allowed) ------------------
__device__ float g_qkv[(size_t)Bb*Nn*QKVC];          // 201 MB
__device__ float g_xr[(size_t)Bb*Nn*DIM];            // tf32-rounded x, 100 MB
__device__ float g_wqkv[DIM*QKVC];                   // tf32-rounded W_qkv
__device__ float g_wproj[DIM*DIM];                   // tf32-rounded W_proj
__device__ float g_nsum[Bb*QKVC];
__device__ float g_inv[Bb*QKVC];
__device__ float g_P[NCHUNK][Bb*HEADS*HD*HD];        // attn partials, 25 MB
__device__ float g_attn[(size_t)Bb*HEADS*HD*HD];     // softmaxed attn (tf32-rounded)
__device__ float g_tmp[(size_t)Bb*Nn*DIM];           // pre-projection output (tf32-rounded)

// ------------------ helpers ------------------
__device__ __forceinline__ uint32_t f2tf32(float x) {
    uint32_t r;
    asm("cvt.rna.tf32.f32 %0, %1;" : "=r"(r) : "f"(x));
    return r;
}
__device__ __forceinline__ float roundtf(float x) {
    return __uint_as_float(f2tf32(x));
}
__device__ __forceinline__ void cp16(void* dst, const void* src) {
    uint32_t d = (uint32_t)__cvta_generic_to_shared(dst);
    asm volatile("cp.async.cg.shared.global [%0], [%1], 16;" :: "r"(d), "l"(src));
}
__device__ __forceinline__ void mma_tf32(float* c, const uint32_t* a, const uint32_t* b) {
    asm volatile(
        "mma.sync.aligned.m16n8k8.row.col.f32.tf32.tf32.f32 "
        "{%0,%1,%2,%3},{%4,%5,%6,%7},{%8,%9},{%0,%1,%2,%3};"
        : "+f"(c[0]), "+f"(c[1]), "+f"(c[2]), "+f"(c[3])
        : "r"(a[0]), "r"(a[1]), "r"(a[2]), "r"(a[3]), "r"(b[0]), "r"(b[1]));
}

// ------------------ elementwise tf32 rounding ------------------
__global__ void round_tf32(const float* __restrict__ in, float* __restrict__ out, int n4) {
    int i = blockIdx.x * 256 + threadIdx.x;
    if (i < n4) {
        float4 v = ((const float4*)in)[i];
        v.x = roundtf(v.x); v.y = roundtf(v.y);
        v.z = roundtf(v.z); v.w = roundtf(v.w);
        ((float4*)out)[i] = v;
    }
}

// ------------------ tf32 GEMM, cp.async double-buffered, 128x128x32 ------------------
// Inputs must be pre-rounded to tf32 values. Dynamic smem: 2*(128*36 + 32*136)*4 B.
#define AST 36
#define BST 136
#define GEMM_SMEM (2*(128*AST + 32*BST)*4)

template<int BIAS>
__global__ __launch_bounds__(256)
void tf32gemm_db(const float* __restrict__ A, const float* __restrict__ Bm,
                 const float* __restrict__ bias, float* __restrict__ C,
                 int M, int N, int K)
{
    extern __shared__ float sm[];
    float* AsBase = sm;                 // [2][128*AST]
    float* BsBase = sm + 2 * 128 * AST; // [2][32*BST]

    const int tid  = threadIdx.x;
    const int m0   = blockIdx.y * 128, n0 = blockIdx.x * 128;
    const int warp = tid >> 5, lane = tid & 31;
    const int wm   = warp >> 1, wn = warp & 1;
    const int g    = lane >> 2, tg = lane & 3;

    float acc[2][8][4];
#pragma unroll
    for (int mt = 0; mt < 2; mt++)
#pragma unroll
        for (int nt = 0; nt < 8; nt++)
#pragma unroll
            for (int i = 0; i < 4; i++) acc[mt][nt][i] = 0.f;

    // cp.async mapping: A tile 128x32 (8 chunks/row), B tile 32x128 (32 chunks/row)
    const int arow = tid >> 1, acol = (tid & 1) * 16;
    const int brow = tid >> 3, bcol = (tid & 7) * 16;
    const float* Ag = A + (size_t)(m0 + arow) * K + acol;
    const float* Bg = Bm + (size_t)brow * N + n0 + bcol;
    float* Asd = AsBase + arow * AST + acol;
    float* Bsd = BsBase + brow * BST + bcol;

    const int KT = K / 32;

    // prologue: stage 0
    {
#pragma unroll
        for (int i = 0; i < 4; i++) cp16(Asd + i * 4, Ag + i * 4);
#pragma unroll
        for (int i = 0; i < 4; i++) cp16(Bsd + i * 4, Bg + i * 4);
        asm volatile("cp.async.commit_group;");
    }

    for (int kt = 0; kt < KT; kt++) {
        const int st = kt & 1;
        if (kt + 1 < KT) {
            const int st2 = st ^ 1;
            const float* Ap = Ag + (kt + 1) * 32;
            const float* Bp = Bg + (size_t)(kt + 1) * 32 * N;
            float* Ad = Asd + st2 * 128 * AST;
            float* Bd = Bsd + st2 * 32 * BST;
#pragma unroll
            for (int i = 0; i < 4; i++) cp16(Ad + i * 4, Ap + i * 4);
#pragma unroll
            for (int i = 0; i < 4; i++) cp16(Bd + i * 4, Bp + i * 4);
            asm volatile("cp.async.commit_group;");
            asm volatile("cp.async.wait_group 1;");
        } else {
            asm volatile("cp.async.wait_group 0;");
        }
        __syncthreads();

        const uint32_t* As = (const uint32_t*)(AsBase + st * 128 * AST);
        const uint32_t* Bs = (const uint32_t*)(BsBase + st * 32 * BST);
#pragma unroll
        for (int ks = 0; ks < 4; ks++) {
            const int kb = ks * 8;
            uint32_t af[2][4];
#pragma unroll
            for (int mt = 0; mt < 2; mt++) {
                int mr = wm * 32 + mt * 16 + g;
                af[mt][0] = As[(size_t)mr * AST + kb + tg];
                af[mt][1] = As[(size_t)(mr + 8) * AST + kb + tg];
                af[mt][2] = As[(size_t)mr * AST + kb + tg + 4];
                af[mt][3] = As[(size_t)(mr + 8) * AST + kb + tg + 4];
            }
            uint32_t bf[8][2];
#pragma unroll
            for (int nt = 0; nt < 8; nt++) {
                int nc = wn * 64 + nt * 8 + g;
                bf[nt][0] = Bs[(size_t)(kb + tg) * BST + nc];
                bf[nt][1] = Bs[(size_t)(kb + tg + 4) * BST + nc];
            }
#pragma unroll
            for (int mt = 0; mt < 2; mt++)
#pragma unroll
                for (int nt = 0; nt < 8; nt++) mma_tf32(acc[mt][nt], af[mt], bf[nt]);
        }
        __syncthreads();
    }

#pragma unroll
    for (int mt = 0; mt < 2; mt++) {
#pragma unroll
        for (int half = 0; half < 2; half++) {
            int row = m0 + wm * 32 + mt * 16 + g + half * 8;
#pragma unroll
            for (int nt = 0; nt < 8; nt++) {
                int col = n0 + wn * 64 + nt * 8 + tg * 2;
                float2 o;
                o.x = acc[mt][nt][half * 2 + 0];
                o.y = acc[mt][nt][half * 2 + 1];
                if (BIAS) { o.x += bias[col]; o.y += bias[col + 1]; }
                *(float2*)&C[(size_t)row * N + col] = o;
            }
        }
    }
}

// ------------------ norms ------------------
__global__ void zero_nsum() {
    int i = blockIdx.x * 256 + threadIdx.x;
    if (i < Bb * QKVC) g_nsum[i] = 0.f;
}

__global__ __launch_bounds__(256)
void partial_norm()
{
    int col = blockIdx.x * 256 + threadIdx.x;
    int ch = blockIdx.y, b = blockIdx.z;
    const float* p = g_qkv + ((size_t)b * Nn + (size_t)ch * CHUNK) * QKVC + col;
    float s = 0.f;
    for (int n = 0; n < CHUNK; n++) {
        float v = p[(size_t)n * QKVC];
        s += v * v;
    }
    atomicAdd(&g_nsum[b * QKVC + col], s);
}

__global__ void inv_norm() {
    int i = blockIdx.x * 256 + threadIdx.x;
    if (i < Bb * QKVC) {
        float nr = sqrtf(g_nsum[i]);
        g_inv[i] = 1.f / fmaxf(nr, EPS);
    }
}

// ------------------ attn partials via tf32 mma: per (h,b,chunk) ------------------
// C[c,c'] = sum_n q[n,c] * k[n,c'], K = 512 tokens per chunk.
__global__ __launch_bounds__(256)
void attn_mma()
{
    int h = blockIdx.x, b = blockIdx.y, ch = blockIdx.z;
    __shared__ uint32_t Qs[32][136];
    __shared__ uint32_t Ks[32][136];

    const int tid  = threadIdx.x;
    const int warp = tid >> 5, lane = tid & 31;
    const int wm   = warp >> 1, wn = warp & 1;
    const int g    = lane >> 2, tg = lane & 3;

    float acc[2][8][4];
#pragma unroll
    for (int mt = 0; mt < 2; mt++)
#pragma unroll
        for (int nt = 0; nt < 8; nt++)
#pragma unroll
            for (int i = 0; i < 4; i++) acc[mt][nt][i] = 0.f;

    const float* qbase = g_qkv + ((size_t)b * Nn + (size_t)ch * CHUNK) * QKVC + h * HD;
    const float* kbase = qbase + DIM;

    const int lrow = tid >> 3;          // 0..31 token row
    const int lcb  = (tid & 7) * 16;    // 16 channels per thread

    for (int n0 = 0; n0 < CHUNK; n0 += 32) {
        const float* qp = qbase + (size_t)(n0 + lrow) * QKVC + lcb;
        const float* kp = kbase + (size_t)(n0 + lrow) * QKVC + lcb;
#pragma unroll
        for (int i = 0; i < 4; i++) {
            float4 qv = *(const float4*)(qp + i * 4);
            Qs[lrow][lcb + i * 4 + 0] = f2tf32(qv.x);
            Qs[lrow][lcb + i * 4 + 1] = f2tf32(qv.y);
            Qs[lrow][lcb + i * 4 + 2] = f2tf32(qv.z);
            Qs[lrow][lcb + i * 4 + 3] = f2tf32(qv.w);
            float4 kv = *(const float4*)(kp + i * 4);
            Ks[lrow][lcb + i * 4 + 0] = f2tf32(kv.x);
            Ks[lrow][lcb + i * 4 + 1] = f2tf32(kv.y);
            Ks[lrow][lcb + i * 4 + 2] = f2tf32(kv.z);
            Ks[lrow][lcb + i * 4 + 3] = f2tf32(kv.w);
        }
        __syncthreads();
#pragma unroll
        for (int ks = 0; ks < 4; ks++) {
            const int kb = ks * 8;
            uint32_t af[2][4];
#pragma unroll
            for (int mt = 0; mt < 2; mt++) {
                int cm = wm * 32 + mt * 16 + g;
                af[mt][0] = Qs[kb + tg][cm];
                af[mt][1] = Qs[kb + tg][cm + 8];
                af[mt][2] = Qs[kb + tg + 4][cm];
                af[mt][3] = Qs[kb + tg + 4][cm + 8];
            }
            uint32_t bf[8][2];
#pragma unroll
            for (int nt = 0; nt < 8; nt++) {
                int nc = wn * 64 + nt * 8 + g;
                bf[nt][0] = Ks[kb + tg][nc];
                bf[nt][1] = Ks[kb + tg + 4][nc];
            }
#pragma unroll
            for (int mt = 0; mt < 2; mt++)
#pragma unroll
                for (int nt = 0; nt < 8; nt++) mma_tf32(acc[mt][nt], af[mt], bf[nt]);
        }
        __syncthreads();
    }

    float* Pp = &g_P[ch][(size_t)(b * HEADS + h) * HD * HD];
#pragma unroll
    for (int mt = 0; mt < 2; mt++) {
#pragma unroll
        for (int half = 0; half < 2; half++) {
            int row = wm * 32 + mt * 16 + g + half * 8;
#pragma unroll
            for (int nt = 0; nt < 8; nt++) {
                int col = wn * 64 + nt * 8 + tg * 2;
                float2 o;
                o.x = acc[mt][nt][half * 2 + 0];
                o.y = acc[mt][nt][half * 2 + 1];
                *(float2*)&Pp[(size_t)row * HD + col] = o;
            }
        }
    }
}

// ------------------ sum partials + scale + softmax (rounds output to tf32) ------------------
__global__ __launch_bounds__(128)
void softmax_rows(const float* __restrict__ temperature)
{
    int c = blockIdx.x, h = blockIdx.y, b = blockIdx.z;
    int d = threadIdx.x;
    size_t off = ((size_t)(b * HEADS + h) * HD + c) * HD + d;

    float s = 0.f;
#pragma unroll
    for (int ch = 0; ch < NCHUNK; ch++) s += g_P[ch][off];

    float scale = g_inv[b * QKVC + h * HD + c] *
                  g_inv[b * QKVC + DIM + h * HD + d] *
                  temperature[h];
    float val = s * scale;

    __shared__ float red[128];
    red[d] = val;
    __syncthreads();
    for (int o = 64; o >= 1; o >>= 1) {
        if (d < o) red[d] = fmaxf(red[d], red[d + o]);
        __syncthreads();
    }
    float mx = red[0];
    __syncthreads();
    float e = expf(val - mx);
    red[d] = e;
    __syncthreads();
    for (int o = 64; o >= 1; o >>= 1) {
        if (d < o) red[d] += red[d + o];
        __syncthreads();
    }
    float inv = 1.f / red[0];
    g_attn[off] = roundtf(e * inv);
}

// ------------------ out_tmp = attn @ v via tf32 mma ------------------
// C[token, c] = sum_d y[token, d] * attn[c, d]; per (b,h), 128-token tiles.
__global__ __launch_bounds__(256)
void av_mma(const float* __restrict__ y)
{
    int mblk = blockIdx.x, h = blockIdx.y, b = blockIdx.z;
    __shared__ uint32_t Ys[128][36];
    __shared__ uint32_t At[128][36];   // attn [c][d-tile]

    const int tid  = threadIdx.x;
    const int warp = tid >> 5, lane = tid & 31;
    const int wm   = warp >> 1, wn = warp & 1;
    const int g    = lane >> 2, tg = lane & 3;

    float acc[2][8][4];
#pragma unroll
    for (int mt = 0; mt < 2; mt++)
#pragma unroll
        for (int nt = 0; nt < 8; nt++)
#pragma unroll
            for (int i = 0; i < 4; i++) acc[mt][nt][i] = 0.f;

    const int m0 = mblk * 128;
    const float* ybase = y + ((size_t)b * Nn + m0) * DIM + h * HD;
    const float* attnp = g_attn + (size_t)(b * HEADS + h) * HD * HD;

    const int lrow = tid >> 1;           // 0..127
    const int lcb  = (tid & 1) * 16;     // 16 d per thread

    for (int d0 = 0; d0 < HD; d0 += 32) {
        const float* yp = ybase + (size_t)lrow * DIM + d0 + lcb;
        const float* ap = attnp + (size_t)lrow * HD + d0 + lcb;
#pragma unroll
        for (int i = 0; i < 4; i++) {
            float4 yv = *(const float4*)(yp + i * 4);
            Ys[lrow][lcb + i * 4 + 0] = f2tf32(yv.x);
            Ys[lrow][lcb + i * 4 + 1] = f2tf32(yv.y);
            Ys[lrow][lcb + i * 4 + 2] = f2tf32(yv.z);
            Ys[lrow][lcb + i * 4 + 3] = f2tf32(yv.w);
            // attn already tf32-rounded by softmax
            *(uint4*)&At[lrow][lcb + i * 4] = *(const uint4*)(ap + i * 4);
        }
        __syncthreads();
#pragma unroll
        for (int ks = 0; ks < 4; ks++) {
            const int kb = ks * 8;
            uint32_t af[2][4];
#pragma unroll
            for (int mt = 0; mt < 2; mt++) {
                int mr = wm * 32 + mt * 16 + g;
                af[mt][0] = Ys[mr][kb + tg];
                af[mt][1] = Ys[mr + 8][kb + tg];
                af[mt][2] = Ys[mr][kb + tg + 4];
                af[mt][3] = Ys[mr + 8][kb + tg + 4];
            }
            uint32_t bf[8][2];
#pragma unroll
            for (int nt = 0; nt < 8; nt++) {
                int nc = wn * 64 + nt * 8 + g;
                bf[nt][0] = At[nc][kb + tg];
                bf[nt][1] = At[nc][kb + tg + 4];
            }
#pragma unroll
            for (int mt = 0; mt < 2; mt++)
#pragma unroll
                for (int nt = 0; nt < 8; nt++) mma_tf32(acc[mt][nt], af[mt], bf[nt]);
        }
        __syncthreads();
    }

    // epilogue: write tf32-rounded (feeds proj GEMM)
#pragma unroll
    for (int mt = 0; mt < 2; mt++) {
#pragma unroll
        for (int half = 0; half < 2; half++) {
            int row = m0 + wm * 32 + mt * 16 + g + half * 8;
#pragma unroll
            for (int nt = 0; nt < 8; nt++) {
                int col = wn * 64 + nt * 8 + tg * 2;
                float2 o;
                o.x = roundtf(acc[mt][nt][half * 2 + 0]);
                o.y = roundtf(acc[mt][nt][half * 2 + 1]);
                *(float2*)&g_tmp[((size_t)b * Nn + row) * DIM + h * HD + col] = o;
            }
        }
    }
}

// ------------------ launch ------------------
extern "C" void kernel_launch(void* const* d_in, const int* in_sizes, int n_in,
                              void* d_out, int out_size)
{
    const float* x     = (const float*)d_in[0];
    const float* y     = (const float*)d_in[1];
    const float* W_qkv = (const float*)d_in[2];
    const float* temp  = (const float*)d_in[3];
    const float* W_prj = (const float*)d_in[4];
    const float* b_prj = (const float*)d_in[5];
    float* out = (float*)d_out;

    float *qkv_p, *tmp_p, *xr_p, *wqkv_p, *wproj_p;
    cudaGetSymbolAddress((void**)&qkv_p, g_qkv);
    cudaGetSymbolAddress((void**)&tmp_p, g_tmp);
    cudaGetSymbolAddress((void**)&xr_p, g_xr);
    cudaGetSymbolAddress((void**)&wqkv_p, g_wqkv);
    cudaGetSymbolAddress((void**)&wproj_p, g_wproj);

    static bool attr_done = false;
    if (!attr_done) {
        cudaFuncSetAttribute(tf32gemm_db<0>, cudaFuncAttributeMaxDynamicSharedMemorySize, GEMM_SMEM);
        cudaFuncSetAttribute(tf32gemm_db<1>, cudaFuncAttributeMaxDynamicSharedMemorySize, GEMM_SMEM);
        attr_done = true;
    }

    // 0. pre-round operands to tf32 values
    {
        int n4x = Bb * Nn * DIM / 4;
        round_tf32<<<(n4x + 255) / 256, 256>>>(x, xr_p, n4x);
        int n4q = DIM * QKVC / 4;
        round_tf32<<<(n4q + 255) / 256, 256>>>(W_qkv, wqkv_p, n4q);
        int n4p = DIM * DIM / 4;
        round_tf32<<<(n4p + 255) / 256, 256>>>(W_prj, wproj_p, n4p);
    }

    // 1. qkv = x @ W_qkv  (tf32 tensor cores, cp.async double-buffered)
    tf32gemm_db<0><<<dim3(QKVC / 128, (Bb * Nn) / 128), 256, GEMM_SMEM>>>(
        xr_p, wqkv_p, nullptr, qkv_p, Bb * Nn, QKVC, DIM);

    // 2. column norms of q,k over token dim (fp32, from un-rounded qkv output)
    zero_nsum<<<(Bb * QKVC + 255) / 256, 256>>>();
    partial_norm<<<dim3(QKVC / 256, NCHUNK, Bb), 256>>>();
    inv_norm<<<(Bb * QKVC + 255) / 256, 256>>>();

    // 3. attn partials (tf32 mma)
    attn_mma<<<dim3(HEADS, Bb, NCHUNK), 256>>>();

    // 4. sum + scale + softmax (writes tf32-rounded attn)
    softmax_rows<<<dim3(HD, HEADS, Bb), 128>>>(temp);

    // 5. out_tmp = attn @ v (tf32 mma, writes tf32-rounded)
    av_mma<<<dim3(Nn / 128, HEADS, Bb), 256>>>(y);

    // 6. out = out_tmp @ W_proj + b (tf32 tensor cores)
    tf32gemm_db<1><<<dim3(DIM / 128, (Bb * Nn) / 128), 256, GEMM_SMEM>>>(
        tmp_p, wproj_p, b_prj, out, Bb * Nn, DIM, DIM);
}

// round 12
// speedup vs baseline: 2.8417x; 1.5001x over previous
#include <cuda_runtime.h>
#include <math.h>
#include <stdint.h>

#define Bb 8
#define Nn 4096
#define DIM 768
#define HEADS 6
#define HD 128
#define QKVC 1536
#define NCHUNK 8
#define CHUNK (Nn/NCHUNK)   // 512
#define EPS 1e-12f

// ------------------ scratch (device globals: no allocs allowed) ------------------
__device__ float g_qkv[(size_t)Bb*Nn*QKVC];          // 201 MB (normal row-major)
__device__ float g_xr[(size_t)Bb*Nn*DIM];            // packed-A x (tf32), 100 MB
__device__ float g_wqkv[DIM*QKVC];                   // packed-B W_qkv (tf32)
__device__ float g_wproj[DIM*DIM];                   // packed-B W_proj (tf32)
__device__ float g_nsum[Bb*QKVC];
__device__ float g_inv[Bb*QKVC];
__device__ float g_P[NCHUNK][Bb*HEADS*HD*HD];        // attn partials, 25 MB
__device__ float g_attn[(size_t)Bb*HEADS*HD*HD];     // softmaxed attn (tf32-rounded)
__device__ float g_tmp[(size_t)Bb*Nn*DIM];           // packed-A pre-projection output

// ------------------ helpers ------------------
__device__ __forceinline__ uint32_t f2tf32(float x) {
    uint32_t r;
    asm("cvt.rna.tf32.f32 %0, %1;" : "=r"(r) : "f"(x));
    return r;
}
__device__ __forceinline__ float roundtf(float x) {
    return __uint_as_float(f2tf32(x));
}
__device__ __forceinline__ void cp16(void* dst, const void* src) {
    uint32_t d = (uint32_t)__cvta_generic_to_shared(dst);
    asm volatile("cp.async.cg.shared.global [%0], [%1], 16;" :: "r"(d), "l"(src));
}
__device__ __forceinline__ void mma4(float* c, const uint4& a, uint32_t b0, uint32_t b1) {
    asm volatile(
        "mma.sync.aligned.m16n8k8.row.col.f32.tf32.tf32.f32 "
        "{%0,%1,%2,%3},{%4,%5,%6,%7},{%8,%9},{%0,%1,%2,%3};"
        : "+f"(c[0]), "+f"(c[1]), "+f"(c[2]), "+f"(c[3])
        : "r"(a.x), "r"(a.y), "r"(a.z), "r"(a.w), "r"(b0), "r"(b1));
}

// packed-A element index: A[M][K] -> tiles [M/128][K/32][4096 floats]
// within tile: idx = (((ks*8+mg)*8+g)*4+tg)*4 + j,  j = khalf*2 + rowhalf
__device__ __forceinline__ size_t aidx(size_t m, int k, int KT) {
    size_t mt = m >> 7; int ml = (int)(m & 127);
    int kt = k >> 5, kl = k & 31;
    int ks = kl >> 3, kk = kl & 7, tg = kk & 3, kh = kk >> 2;
    int mg = ml >> 4, rh = (ml >> 3) & 1, gg = ml & 7;
    return ((mt * KT + kt) << 12) + (((((ks << 3) + mg) << 3) + gg) << 4) + (tg << 2) + (kh * 2 + rh);
}

// ------------------ pack kernels (round to tf32 + fragment order) ------------------
// A pack: src [M,K] row-major -> dst packed tiles
__global__ void pack_a(const float* __restrict__ src, float* __restrict__ dst,
                       int M, int K)
{
    int KT = K >> 5;
    size_t q = (size_t)blockIdx.x * 256 + threadIdx.x;       // float4 index
    size_t total = ((size_t)M * K) >> 2;
    if (q >= total) return;
    size_t tile = q >> 10;
    int qi = (int)(q & 1023);
    size_t mt = tile / KT; int kt = (int)(tile % KT);
    int tg = qi & 3, gg = (qi >> 2) & 7, mg = (qi >> 5) & 7, ks = qi >> 8;
    float4 o; float* po = (float*)&o;
#pragma unroll
    for (int j = 0; j < 4; j++) {
        int kh = j >> 1, rh = j & 1;
        size_t m = mt * 128 + mg * 16 + rh * 8 + gg;
        int k = kt * 32 + ks * 8 + kh * 4 + tg;
        po[j] = roundtf(src[m * K + k]);
    }
    ((float4*)dst)[q] = o;
}

// B pack: src [K,N] row-major -> dst packed tiles [N/128][K/32][4096]
// within tile: idx = (((kp*16+ng)*8+g)*4+tg)*4 + j,  j = (ks%2)*2 + khalf
__global__ void pack_b(const float* __restrict__ src, float* __restrict__ dst,
                       int K, int N)
{
    int KT = K >> 5;
    size_t q = (size_t)blockIdx.x * 256 + threadIdx.x;
    size_t total = ((size_t)K * N) >> 2;
    if (q >= total) return;
    size_t tile = q >> 10;
    int qi = (int)(q & 1023);
    size_t nt0 = tile / KT; int kt = (int)(tile % KT);
    int tg = qi & 3, gg = (qi >> 2) & 7, ng = (qi >> 5) & 15, kp = qi >> 9;
    float4 o; float* po = (float*)&o;
#pragma unroll
    for (int j = 0; j < 4; j++) {
        int s = j >> 1, kh = j & 1;
        int k = kt * 32 + (kp * 2 + s) * 8 + kh * 4 + tg;
        size_t n = nt0 * 128 + ng * 8 + gg;
        po[j] = roundtf(src[(size_t)k * N + n]);
    }
    ((float4*)dst)[q] = o;
}

// ------------------ packed tf32 GEMM: 128x128x32 tile, 3-stage cp.async ------------------
#define STAGES 3
#define TILE_F 8192    // floats per stage: A 4096 + B 4096
#define GEMM_SMEM (STAGES * TILE_F * 4)

template<int BIAS>
__global__ __launch_bounds__(256, 2)
void tf32gemm_pk(const float* __restrict__ A, const float* __restrict__ B,
                 const float* __restrict__ bias, float* __restrict__ C,
                 int M, int N, int K)
{
    extern __shared__ float sm[];
    const int KT = K >> 5;
    const int tid  = threadIdx.x;
    const int warp = tid >> 5, lane = tid & 31;
    const int wm   = warp >> 1, wn = warp & 1;
    const int g    = lane >> 2, tg = lane & 3;

    const float* Atile = A + (size_t)blockIdx.y * KT * 4096;
    const float* Btile = B + (size_t)blockIdx.x * KT * 4096;

    float acc[2][8][4];
#pragma unroll
    for (int mt = 0; mt < 2; mt++)
#pragma unroll
        for (int nt = 0; nt < 8; nt++)
#pragma unroll
            for (int i = 0; i < 4; i++) acc[mt][nt][i] = 0.f;

    // staging: copy one 32KB (A+B) stage; fully coalesced 16B chunks
    auto stage_copy = [&](int kt, int buf) {
        float* d = sm + buf * TILE_F;
        const float* sa = Atile + (size_t)kt * 4096;
        const float* sb = Btile + (size_t)kt * 4096;
#pragma unroll
        for (int i = 0; i < 4; i++)
            cp16(d + (size_t)(tid + i * 256) * 4, sa + (size_t)(tid + i * 256) * 4);
#pragma unroll
        for (int i = 0; i < 4; i++)
            cp16(d + 4096 + (size_t)(tid + i * 256) * 4, sb + (size_t)(tid + i * 256) * 4);
        asm volatile("cp.async.commit_group;");
    };

    stage_copy(0, 0);
    if (KT > 1) stage_copy(1, 1);

    for (int kt = 0; kt < KT; kt++) {
        if (kt + 1 < KT) asm volatile("cp.async.wait_group 1;");
        else             asm volatile("cp.async.wait_group 0;");
        __syncthreads();
        if (kt + 2 < KT) stage_copy(kt + 2, (kt + 2) % STAGES);

        const float* As = sm + (kt % STAGES) * TILE_F;
        const float* Bs = As + 4096;

#pragma unroll
        for (int kp = 0; kp < 2; kp++) {
            uint4 bf[8];
#pragma unroll
            for (int nt = 0; nt < 8; nt++)
                bf[nt] = *(const uint4*)(Bs + ((((kp * 16 + wn * 8 + nt) * 8 + g) * 4 + tg) << 2));
#pragma unroll
            for (int s = 0; s < 2; s++) {
                const int ks = kp * 2 + s;
                uint4 a0 = *(const uint4*)(As + ((((ks * 8 + wm * 2 + 0) * 8 + g) * 4 + tg) << 2));
                uint4 a1 = *(const uint4*)(As + ((((ks * 8 + wm * 2 + 1) * 8 + g) * 4 + tg) << 2));
#pragma unroll
                for (int nt = 0; nt < 8; nt++) {
                    uint32_t b0 = s ? bf[nt].z : bf[nt].x;
                    uint32_t b1 = s ? bf[nt].w : bf[nt].y;
                    mma4(acc[0][nt], a0, b0, b1);
                    mma4(acc[1][nt], a1, b0, b1);
                }
            }
        }
    }

    // epilogue: C normal row-major
    const int m0 = blockIdx.y * 128, n0 = blockIdx.x * 128;
#pragma unroll
    for (int mt = 0; mt < 2; mt++) {
#pragma unroll
        for (int half = 0; half < 2; half++) {
            int row = m0 + wm * 32 + mt * 16 + g + half * 8;
#pragma unroll
            for (int nt = 0; nt < 8; nt++) {
                int col = n0 + wn * 64 + nt * 8 + tg * 2;
                float2 o;
                o.x = acc[mt][nt][half * 2 + 0];
                o.y = acc[mt][nt][half * 2 + 1];
                if (BIAS) { o.x += bias[col]; o.y += bias[col + 1]; }
                *(float2*)&C[(size_t)row * N + col] = o;
            }
        }
    }
}

// ------------------ norms ------------------
__global__ void zero_nsum() {
    int i = blockIdx.x * 256 + threadIdx.x;
    if (i < Bb * QKVC) g_nsum[i] = 0.f;
}

__global__ __launch_bounds__(256)
void partial_norm()
{
    int col = blockIdx.x * 256 + threadIdx.x;
    int ch = blockIdx.y, b = blockIdx.z;
    const float* p = g_qkv + ((size_t)b * Nn + (size_t)ch * CHUNK) * QKVC + col;
    float s = 0.f;
    for (int n = 0; n < CHUNK; n++) {
        float v = p[(size_t)n * QKVC];
        s += v * v;
    }
    atomicAdd(&g_nsum[b * QKVC + col], s);
}

__global__ void inv_norm() {
    int i = blockIdx.x * 256 + threadIdx.x;
    if (i < Bb * QKVC) {
        float nr = sqrtf(g_nsum[i]);
        g_inv[i] = 1.f / fmaxf(nr, EPS);
    }
}

// ------------------ attn partials via tf32 mma: per (h,b,chunk) ------------------
__global__ __launch_bounds__(256)
void attn_mma()
{
    int h = blockIdx.x, b = blockIdx.y, ch = blockIdx.z;
    __shared__ uint32_t Qs[32][136];
    __shared__ uint32_t Ks[32][136];

    const int tid  = threadIdx.x;
    const int warp = tid >> 5, lane = tid & 31;
    const int wm   = warp >> 1, wn = warp & 1;
    const int g    = lane >> 2, tg = lane & 3;

    float acc[2][8][4];
#pragma unroll
    for (int mt = 0; mt < 2; mt++)
#pragma unroll
        for (int nt = 0; nt < 8; nt++)
#pragma unroll
            for (int i = 0; i < 4; i++) acc[mt][nt][i] = 0.f;

    const float* qbase = g_qkv + ((size_t)b * Nn + (size_t)ch * CHUNK) * QKVC + h * HD;
    const float* kbase = qbase + DIM;

    const int lrow = tid >> 3;
    const int lcb  = (tid & 7) * 16;

    for (int n0 = 0; n0 < CHUNK; n0 += 32) {
        const float* qp = qbase + (size_t)(n0 + lrow) * QKVC + lcb;
        const float* kp = kbase + (size_t)(n0 + lrow) * QKVC + lcb;
#pragma unroll
        for (int i = 0; i < 4; i++) {
            float4 qv = *(const float4*)(qp + i * 4);
            Qs[lrow][lcb + i * 4 + 0] = f2tf32(qv.x);
            Qs[lrow][lcb + i * 4 + 1] = f2tf32(qv.y);
            Qs[lrow][lcb + i * 4 + 2] = f2tf32(qv.z);
            Qs[lrow][lcb + i * 4 + 3] = f2tf32(qv.w);
            float4 kv = *(const float4*)(kp + i * 4);
            Ks[lrow][lcb + i * 4 + 0] = f2tf32(kv.x);
            Ks[lrow][lcb + i * 4 + 1] = f2tf32(kv.y);
            Ks[lrow][lcb + i * 4 + 2] = f2tf32(kv.z);
            Ks[lrow][lcb + i * 4 + 3] = f2tf32(kv.w);
        }
        __syncthreads();
#pragma unroll
        for (int ks = 0; ks < 4; ks++) {
            const int kb = ks * 8;
            uint32_t af[2][4];
#pragma unroll
            for (int mt = 0; mt < 2; mt++) {
                int cm = wm * 32 + mt * 16 + g;
                af[mt][0] = Qs[kb + tg][cm];
                af[mt][1] = Qs[kb + tg][cm + 8];
                af[mt][2] = Qs[kb + tg + 4][cm];
                af[mt][3] = Qs[kb + tg + 4][cm + 8];
            }
            uint32_t bf[8][2];
#pragma unroll
            for (int nt = 0; nt < 8; nt++) {
                int nc = wn * 64 + nt * 8 + g;
                bf[nt][0] = Ks[kb + tg][nc];
                bf[nt][1] = Ks[kb + tg + 4][nc];
            }
#pragma unroll
            for (int mt = 0; mt < 2; mt++)
#pragma unroll
                for (int nt = 0; nt < 8; nt++) {
                    uint4 a = make_uint4(af[mt][0], af[mt][1], af[mt][2], af[mt][3]);
                    mma4(acc[mt][nt], a, bf[nt][0], bf[nt][1]);
                }
        }
        __syncthreads();
    }

    float* Pp = &g_P[ch][(size_t)(b * HEADS + h) * HD * HD];
#pragma unroll
    for (int mt = 0; mt < 2; mt++) {
#pragma unroll
        for (int half = 0; half < 2; half++) {
            int row = wm * 32 + mt * 16 + g + half * 8;
#pragma unroll
            for (int nt = 0; nt < 8; nt++) {
                int col = wn * 64 + nt * 8 + tg * 2;
                float2 o;
                o.x = acc[mt][nt][half * 2 + 0];
                o.y = acc[mt][nt][half * 2 + 1];
                *(float2*)&Pp[(size_t)row * HD + col] = o;
            }
        }
    }
}

// ------------------ sum partials + scale + softmax (writes tf32-rounded) ------------------
__global__ __launch_bounds__(128)
void softmax_rows(const float* __restrict__ temperature)
{
    int c = blockIdx.x, h = blockIdx.y, b = blockIdx.z;
    int d = threadIdx.x;
    size_t off = ((size_t)(b * HEADS + h) * HD + c) * HD + d;

    float s = 0.f;
#pragma unroll
    for (int ch = 0; ch < NCHUNK; ch++) s += g_P[ch][off];

    float scale = g_inv[b * QKVC + h * HD + c] *
                  g_inv[b * QKVC + DIM + h * HD + d] *
                  temperature[h];
    float val = s * scale;

    __shared__ float red[128];
    red[d] = val;
    __syncthreads();
    for (int o = 64; o >= 1; o >>= 1) {
        if (d < o) red[d] = fmaxf(red[d], red[d + o]);
        __syncthreads();
    }
    float mx = red[0];
    __syncthreads();
    float e = expf(val - mx);
    red[d] = e;
    __syncthreads();
    for (int o = 64; o >= 1; o >>= 1) {
        if (d < o) red[d] += red[d + o];
        __syncthreads();
    }
    float inv = 1.f / red[0];
    g_attn[off] = roundtf(e * inv);
}

// ------------------ out_tmp = attn @ v via tf32 mma; epilogue writes packed-A ------------------
__global__ __launch_bounds__(256)
void av_mma(const float* __restrict__ y)
{
    int mblk = blockIdx.x, h = blockIdx.y, b = blockIdx.z;
    __shared__ uint32_t Ys[128][36];
    __shared__ uint32_t At[128][36];

    const int tid  = threadIdx.x;
    const int warp = tid >> 5, lane = tid & 31;
    const int wm   = warp >> 1, wn = warp & 1;
    const int g    = lane >> 2, tg = lane & 3;

    float acc[2][8][4];
#pragma unroll
    for (int mt = 0; mt < 2; mt++)
#pragma unroll
        for (int nt = 0; nt < 8; nt++)
#pragma unroll
            for (int i = 0; i < 4; i++) acc[mt][nt][i] = 0.f;

    const int m0 = mblk * 128;
    const float* ybase = y + ((size_t)b * Nn + m0) * DIM + h * HD;
    const float* attnp = g_attn + (size_t)(b * HEADS + h) * HD * HD;

    const int lrow = tid >> 1;
    const int lcb  = (tid & 1) * 16;

    for (int d0 = 0; d0 < HD; d0 += 32) {
        const float* yp = ybase + (size_t)lrow * DIM + d0 + lcb;
        const float* ap = attnp + (size_t)lrow * HD + d0 + lcb;
#pragma unroll
        for (int i = 0; i < 4; i++) {
            float4 yv = *(const float4*)(yp + i * 4);
            Ys[lrow][lcb + i * 4 + 0] = f2tf32(yv.x);
            Ys[lrow][lcb + i * 4 + 1] = f2tf32(yv.y);
            Ys[lrow][lcb + i * 4 + 2] = f2tf32(yv.z);
            Ys[lrow][lcb + i * 4 + 3] = f2tf32(yv.w);
            *(uint4*)&At[lrow][lcb + i * 4] = *(const uint4*)(ap + i * 4);
        }
        __syncthreads();
#pragma unroll
        for (int ks = 0; ks < 4; ks++) {
            const int kb = ks * 8;
            uint32_t af[2][4];
#pragma unroll
            for (int mt = 0; mt < 2; mt++) {
                int mr = wm * 32 + mt * 16 + g;
                af[mt][0] = Ys[mr][kb + tg];
                af[mt][1] = Ys[mr + 8][kb + tg];
                af[mt][2] = Ys[mr][kb + tg + 4];
                af[mt][3] = Ys[mr + 8][kb + tg + 4];
            }
            uint32_t bf[8][2];
#pragma unroll
            for (int nt = 0; nt < 8; nt++) {
                int nc = wn * 64 + nt * 8 + g;
                bf[nt][0] = At[nc][kb + tg];
                bf[nt][1] = At[nc][kb + tg + 4];
            }
#pragma unroll
            for (int mt = 0; mt < 2; mt++)
#pragma unroll
                for (int nt = 0; nt < 8; nt++) {
                    uint4 a = make_uint4(af[mt][0], af[mt][1], af[mt][2], af[mt][3]);
                    mma4(acc[mt][nt], a, bf[nt][0], bf[nt][1]);
                }
        }
        __syncthreads();
    }

    // epilogue: write tf32-rounded into packed-A layout of g_tmp (feeds proj GEMM)
#pragma unroll
    for (int mt = 0; mt < 2; mt++) {
#pragma unroll
        for (int half = 0; half < 2; half++) {
            int row = m0 + wm * 32 + mt * 16 + g + half * 8;
            size_t gm = (size_t)b * Nn + row;
#pragma unroll
            for (int nt = 0; nt < 8; nt++) {
                int col = h * HD + wn * 64 + nt * 8 + tg * 2;
                g_tmp[aidx(gm, col,     DIM / 32)] = roundtf(acc[mt][nt][half * 2 + 0]);
                g_tmp[aidx(gm, col + 1, DIM / 32)] = roundtf(acc[mt][nt][half * 2 + 1]);
            }
        }
    }
}

// ------------------ launch ------------------
extern "C" void kernel_launch(void* const* d_in, const int* in_sizes, int n_in,
                              void* d_out, int out_size)
{
    const float* x     = (const float*)d_in[0];
    const float* y     = (const float*)d_in[1];
    const float* W_qkv = (const float*)d_in[2];
    const float* temp  = (const float*)d_in[3];
    const float* W_prj = (const float*)d_in[4];
    const float* b_prj = (const float*)d_in[5];
    float* out = (float*)d_out;

    float *qkv_p, *tmp_p, *xr_p, *wqkv_p, *wproj_p;
    cudaGetSymbolAddress((void**)&qkv_p, g_qkv);
    cudaGetSymbolAddress((void**)&tmp_p, g_tmp);
    cudaGetSymbolAddress((void**)&xr_p, g_xr);
    cudaGetSymbolAddress((void**)&wqkv_p, g_wqkv);
    cudaGetSymbolAddress((void**)&wproj_p, g_wproj);

    static bool attr_done = false;
    if (!attr_done) {
        cudaFuncSetAttribute(tf32gemm_pk<0>, cudaFuncAttributeMaxDynamicSharedMemorySize, GEMM_SMEM);
        cudaFuncSetAttribute(tf32gemm_pk<1>, cudaFuncAttributeMaxDynamicSharedMemorySize, GEMM_SMEM);
        attr_done = true;
    }

    // 0. pack operands (round to tf32 + fragment order)
    {
        size_t n4x = ((size_t)Bb * Nn * DIM) >> 2;
        pack_a<<<(unsigned)((n4x + 255) / 256), 256>>>(x, xr_p, Bb * Nn, DIM);
        size_t n4q = ((size_t)DIM * QKVC) >> 2;
        pack_b<<<(unsigned)((n4q + 255) / 256), 256>>>(W_qkv, wqkv_p, DIM, QKVC);
        size_t n4p = ((size_t)DIM * DIM) >> 2;
        pack_b<<<(unsigned)((n4p + 255) / 256), 256>>>(W_prj, wproj_p, DIM, DIM);
    }

    // 1. qkv = x @ W_qkv  (packed tf32 tensor cores)
    tf32gemm_pk<0><<<dim3(QKVC / 128, (Bb * Nn) / 128), 256, GEMM_SMEM>>>(
        xr_p, wqkv_p, nullptr, qkv_p, Bb * Nn, QKVC, DIM);

    // 2. column norms of q,k over token dim
    zero_nsum<<<(Bb * QKVC + 255) / 256, 256>>>();
    partial_norm<<<dim3(QKVC / 256, NCHUNK, Bb), 256>>>();
    inv_norm<<<(Bb * QKVC + 255) / 256, 256>>>();

    // 3. attn partials (tf32 mma)
    attn_mma<<<dim3(HEADS, Bb, NCHUNK), 256>>>();

    // 4. sum + scale + softmax
    softmax_rows<<<dim3(HD, HEADS, Bb), 128>>>(temp);

    // 5. out_tmp = attn @ v (tf32 mma, writes packed-A)
    av_mma<<<dim3(Nn / 128, HEADS, Bb), 256>>>(y);

    // 6. out = out_tmp @ W_proj + b (packed tf32 tensor cores)
    tf32gemm_pk<1><<<dim3(DIM / 128, (Bb * Nn) / 128), 256, GEMM_SMEM>>>(
        tmp_p, wproj_p, b_prj, out, Bb * Nn, DIM, DIM);
}